// round 14
// baseline (speedup 1.0000x reference)
#include <cuda_runtime.h>
#include <cuda_bf16.h>
#include <cstdint>
#include <math.h>

// ---------------------------------------------------------------- constants
#define BB 4
#define NN 20000
#define SS 2048
#define CC 64
#define DD 64
#define INV_T 1.4285714285714286f
#define C2EXP 2.0609929155556624f   // INV_T * log2(e)

#define TILE_M 64
#define TN 128
#define NCH (SS / TN)          // 16 column chunks
#define TPB (SS / TILE_M)      // 32 row tiles per batch
#define NCTA (BB * TPB)        // 128 loss CTAs

// k_loss dynamic smem layout
#define OFF_A     0                  // 8 KB   (64 rows x 128 B)
#define OFF_B     8192               // 3 x 16 KB (128 rows x 128 B each)
#define OFF_SSUM  (8192 + 3*16384)   // 2*64 floats
#define OFF_SDIAG (OFF_SSUM + 512)   // 64 floats
#define OFF_SLOSS (OFF_SDIAG + 256)  // 64 floats
#define SMEM_K2   (OFF_SLOSS + 256)  // 58368 B

// ---------------------------------------------------------------- scratch
__device__ __align__(256) __nv_bfloat16 g_Vn[(size_t)BB * SS * CC];
__device__ __align__(256) __nv_bfloat16 g_Fn[(size_t)BB * SS * CC];
__device__ int   g_faddr[BB * NN];   // flat voxel index of fusion point, by original id
__device__ float g_partials[NCTA];
__device__ int   g_count;   // zero-init; reset by last CTA each run

// ---------------------------------------------------------------- helpers
__device__ __forceinline__ uint32_t smem_u32(const void* p) {
    uint32_t a;
    asm("{ .reg .u64 t; cvta.to.shared.u64 t, %1; cvt.u32.u64 %0, t; }" : "=r"(a) : "l"(p));
    return a;
}
__device__ __forceinline__ void cpa16(uint32_t dst, const void* src) {
    asm volatile("cp.async.cg.shared.global [%0], [%1], 16;" :: "r"(dst), "l"(src));
}
#define CP_COMMIT() asm volatile("cp.async.commit_group;" ::: "memory")
#define CP_WAIT(n)  asm volatile("cp.async.wait_group %0;" :: "n"(n) : "memory")

#define LDSM4(r0, r1, r2, r3, addr)                                            \
    asm volatile("ldmatrix.sync.aligned.m8n8.x4.shared.b16 {%0,%1,%2,%3}, [%4];" \
                 : "=r"(r0), "=r"(r1), "=r"(r2), "=r"(r3) : "r"(addr))

__device__ __forceinline__ void mma16816(float* c, const uint32_t* a,
                                         uint32_t b0, uint32_t b1) {
    asm volatile(
        "mma.sync.aligned.m16n8k16.row.col.f32.bf16.bf16.f32 "
        "{%0,%1,%2,%3}, {%4,%5,%6,%7}, {%8,%9}, {%0,%1,%2,%3};"
        : "+f"(c[0]), "+f"(c[1]), "+f"(c[2]), "+f"(c[3])
        : "r"(a[0]), "r"(a[1]), "r"(a[2]), "r"(a[3]), "r"(b0), "r"(b1));
}
__device__ __forceinline__ float ex2f(float x) {
    float r; asm("ex2.approx.f32 %0, %1;" : "=f"(r) : "f"(x)); return r;
}

// ---------------------------------------------------------------- kernel S
// scatter flattened fusion voxel addresses: g_faddr[b][shuf[j]] = flat(fcoor[j]>>3)
// one element per thread, 313 CTAs.
__global__ __launch_bounds__(256) void kS(
    const int* __restrict__ fcoor, const int* __restrict__ shuf)
{
    int i = blockIdx.x * 256 + threadIdx.x;
    if (i < BB * NN) {
        int b = i / NN;
        int v = shuf[i];
        const int* cp = fcoor + (size_t)i * 3;
        int c0 = cp[0] >> 3, c1 = cp[1] >> 3, c2 = cp[2] >> 3;
        g_faddr[b * NN + v] = ((b * DD + c0) * DD + c1) * DD + c2;
    }
}

// ---------------------------------------------------------------- kernel G
// Combined V + F gather: one row per warp, two independent load trees
// hanging off the shared samp value (doubles per-warp MLP at equal depth).
__global__ __launch_bounds__(256) void kG(
    const float* __restrict__ dv, const int* __restrict__ vcoor,
    const float* __restrict__ df, const int* __restrict__ samp_idx)
{
    const int tid = threadIdx.x;
    const int w   = tid >> 5;
    const int l   = tid & 31;

    int r = blockIdx.x * 8 + w;        // 0..8191
    int b = r >> 11, s = r & 2047;
    int samp = __ldg(&samp_idx[b * SS + s]);

    // issue both address chains back-to-back (independent after samp)
    const int* cpv = vcoor + ((size_t)b * NN + samp) * 3;
    int c0 = cpv[0], c1 = cpv[1], c2 = cpv[2];
    int fflat = __ldg(&g_faddr[b * NN + samp]);

    const float* vsrc = dv + ((((size_t)b * DD + (c0 >> 3)) * DD + (c1 >> 3)) * DD + (c2 >> 3)) * (size_t)CC;
    const float* fsrc = df + (size_t)fflat * CC;

    // four independent 128B loads in flight
    float a0 = vsrc[l], a1 = vsrc[l + 32];
    float b0 = fsrc[l], b1 = fsrc[l + 32];

    float sv = a0 * a0 + a1 * a1;
    float sf = b0 * b0 + b1 * b1;
    #pragma unroll
    for (int o = 16; o; o >>= 1) {
        sv += __shfl_xor_sync(0xffffffffu, sv, o);
        sf += __shfl_xor_sync(0xffffffffu, sf, o);
    }
    float iv = 1.0f / fmaxf(sqrtf(sv), 1e-12f);
    float jf = 1.0f / fmaxf(sqrtf(sf), 1e-12f);

    size_t rb = (size_t)r * CC;
    g_Vn[rb + l]      = __float2bfloat16(a0 * iv);
    g_Vn[rb + l + 32] = __float2bfloat16(a1 * iv);
    g_Fn[rb + l]      = __float2bfloat16(b0 * jf);
    g_Fn[rb + l + 32] = __float2bfloat16(b1 * jf);
}

// ---------------------------------------------------------------- kernel 2
// Fused bf16 mma.sync GEMM (64 x 2048 x 64 per CTA) + exp/rowsum/diag + loss.
// 3-buffer cp.async pipeline: ONE __syncthreads per chunk.  (unchanged)
__global__ __launch_bounds__(256, 1) void k_loss(float* __restrict__ out) {
    extern __shared__ __align__(128) unsigned char dsm[];
    float* ssum  = (float*)(dsm + OFF_SSUM);   // [2][64]
    float* sdiag = (float*)(dsm + OFF_SDIAG);  // [64]
    float* sloss = (float*)(dsm + OFF_SLOSS);  // [64]

    const int tid = threadIdx.x;
    const int w   = tid >> 5;
    const int l   = tid & 31;
    const int cta = blockIdx.x;
    const int b      = cta >> 5;
    const int mytile = cta & 31;
    const int g  = w >> 2;          // column half group
    const int wr = (w & 3) * 16;    // warp row base (local)

    const __nv_bfloat16* Ag = g_Vn + ((size_t)b * SS + (size_t)mytile * TILE_M) * CC;
    const __nv_bfloat16* Fg = g_Fn + (size_t)b * SS * CC;

    const uint32_t sAu = smem_u32(dsm + OFF_A);
    const uint32_t sBu[3] = { smem_u32(dsm + OFF_B),
                              smem_u32(dsm + OFF_B + 16384),
                              smem_u32(dsm + OFF_B + 32768) };

    // prologue: G0 = A + B0, G1 = B1
    for (int i = tid; i < 512; i += 256) {
        int r = i >> 3, c = i & 7;
        cpa16(sAu + r * 128 + ((c ^ (r & 7)) << 4), (const char*)Ag + r * 128 + c * 16);
    }
    for (int i = tid; i < 1024; i += 256) {
        int r = i >> 3, c = i & 7;
        cpa16(sBu[0] + r * 128 + ((c ^ (r & 7)) << 4), (const char*)Fg + r * 128 + c * 16);
    }
    CP_COMMIT();
    for (int i = tid; i < 1024; i += 256) {
        int r = i >> 3, c = i & 7;
        cpa16(sBu[1] + r * 128 + ((c ^ (r & 7)) << 4),
              (const char*)Fg + (size_t)TN * 128 + r * 128 + c * 16);
    }
    CP_COMMIT();
    CP_WAIT(1);          // A + B0 landed
    __syncthreads();

    // A fragments (constant across all chunks)
    uint32_t afr[4][4];
    {
        int row = wr + (l & 15);
        #pragma unroll
        for (int kk = 0; kk < 4; kk++) {
            int kb = kk * 32 + (l >> 4) * 16;
            uint32_t ad = sAu + row * 128 + (((kb >> 4) ^ (row & 7)) << 4);
            LDSM4(afr[kk][0], afr[kk][1], afr[kk][2], afr[kk][3], ad);
        }
    }

    const int r0 = wr + (l >> 2), r1 = r0 + 8;
    const bool mygrp = (g == (mytile & 1));
    const int dct = mytile >> 1;
    float rs0 = 0.f, rs1 = 0.f, d0 = 0.f, d1 = 0.f;

    const int nlane  = (l & 7) + ((l >> 4) << 3);
    const int kblane = ((l >> 3) & 1) * 16;

    for (int ct = 0; ct < NCH; ++ct) {
        CP_WAIT(1);          // group(ct) complete (<=1 outstanding: ct+1)
        __syncthreads();     // visibility + all warps done with buf[(ct+2)%3]

        // prefetch chunk ct+2 into buf[(ct+2)%3] (consumed at iter ct-1)
        if (ct + 2 < NCH) {
            uint32_t dstB = sBu[(ct + 2) % 3];
            const char* src = (const char*)Fg + (size_t)(ct + 2) * TN * 128;
            for (int i = tid; i < 1024; i += 256) {
                int r = i >> 3, c = i & 7;
                cpa16(dstB + r * 128 + ((c ^ (r & 7)) << 4), src + r * 128 + c * 16);
            }
            CP_COMMIT();
        }

        const uint32_t sBc = sBu[ct % 3];
        const bool dg = mygrp && (ct == dct);

        #pragma unroll
        for (int jp = 0; jp < 4; ++jp) {
            float a0[4] = {0.f, 0.f, 0.f, 0.f};
            float a1[4] = {0.f, 0.f, 0.f, 0.f};
            #pragma unroll
            for (int kk = 0; kk < 4; ++kk) {
                int n  = g * 64 + jp * 16 + nlane;
                int kb = kk * 32 + kblane;
                uint32_t ad = sBc + n * 128 + (((kb >> 4) ^ (n & 7)) << 4);
                uint32_t b0, b1, b2, b3;
                LDSM4(b0, b1, b2, b3, ad);
                mma16816(a0, afr[kk], b0, b1);
                mma16816(a1, afr[kk], b2, b3);
            }
            int c00 = jp * 16 + (l & 3) * 2;
            int c10 = c00 + 8;
            if (dg) {
                if (c00     == r0) d0 = a0[0];
                if (c00 + 1 == r0) d0 = a0[1];
                if (c10     == r0) d0 = a1[0];
                if (c10 + 1 == r0) d0 = a1[1];
                if (c00     == r1) d1 = a0[2];
                if (c00 + 1 == r1) d1 = a0[3];
                if (c10     == r1) d1 = a1[2];
                if (c10 + 1 == r1) d1 = a1[3];
            }
            rs0 += ex2f(a0[0] * C2EXP) + ex2f(a0[1] * C2EXP)
                 + ex2f(a1[0] * C2EXP) + ex2f(a1[1] * C2EXP);
            rs1 += ex2f(a0[2] * C2EXP) + ex2f(a0[3] * C2EXP)
                 + ex2f(a1[2] * C2EXP) + ex2f(a1[3] * C2EXP);
        }
    }

    // reduce within quads
    #pragma unroll
    for (int o = 1; o <= 2; o <<= 1) {
        rs0 += __shfl_xor_sync(0xffffffffu, rs0, o);
        rs1 += __shfl_xor_sync(0xffffffffu, rs1, o);
        d0  += __shfl_xor_sync(0xffffffffu, d0, o);
        d1  += __shfl_xor_sync(0xffffffffu, d1, o);
    }
    if ((l & 3) == 0) {
        ssum[g * TILE_M + r0] = rs0;
        ssum[g * TILE_M + r1] = rs1;
        if (mygrp) { sdiag[r0] = d0; sdiag[r1] = d1; }
    }
    __syncthreads();

    if (tid < TILE_M) {
        float tot = ssum[tid] + ssum[TILE_M + tid];
        sloss[tid] = logf(tot) - sdiag[tid] * INV_T;
    }
    __syncthreads();

    if (tid == 0) {
        float part = 0.f;
        #pragma unroll
        for (int i = 0; i < TILE_M; ++i) part += sloss[i];
        g_partials[cta] = part * (1.0f / (float)SS);
        __threadfence();
        int n = atomicAdd(&g_count, 1);
        if (n == NCTA - 1) {
            __threadfence();
            const volatile float* gp = (const volatile float*)g_partials;
            float tot = 0.f;
            for (int i = 0; i < NCTA; ++i) tot += gp[i];
            out[0] = tot;
            g_count = 0;   // reset for next graph replay
        }
    }
}

// ---------------------------------------------------------------- launch
extern "C" void kernel_launch(void* const* d_in, const int* in_sizes, int n_in,
                              void* d_out, int out_size) {
    const float* dv    = (const float*)d_in[0];
    const int*   vcoor = (const int*)  d_in[1];
    const float* df    = (const float*)d_in[2];
    const int*   fcoor = (const int*)  d_in[3];
    const int*   shuf  = (const int*)  d_in[4];
    // d_in[5] = vehicle_points (unused)
    const int*   samp  = (const int*)  d_in[6];

    cudaFuncSetAttribute(k_loss, cudaFuncAttributeMaxDynamicSharedMemorySize, SMEM_K2);

    kS<<<(BB * NN + 255) / 256, 256>>>(fcoor, shuf);
    kG<<<1024, 256>>>(dv, vcoor, df, samp);
    k_loss<<<NCTA, 256, SMEM_K2>>>((float*)d_out);
}